// round 14
// baseline (speedup 1.0000x reference)
#include <cuda_runtime.h>

#define DIM 768
#define NE 8
#define WARPS_PER_BLOCK 8
#define THREADS 256
#define TOK_PER_WARP 3
#define TOK_PER_BLOCK (WARPS_PER_BLOCK * TOK_PER_WARP)  // 24
// DIM/4 = 192 float4 per token row; 192/32 lanes = 6 float4 per lane
#define F4_PER_LANE 6

__global__ __launch_bounds__(THREADS, 5)
void router_kernel(const float* __restrict__ x,
                   const float* __restrict__ W,
                   const float* __restrict__ b,
                   float* __restrict__ out,
                   int n_tokens, int write_idx)
{
    __shared__ float Ws[NE * DIM];
    __shared__ float bs[NE];

    // Stage W (24 KB) + b into shared once per block, vectorized.
    {
        const float4* Wg = reinterpret_cast<const float4*>(W);
        float4* Wsm = reinterpret_cast<float4*>(Ws);
        #pragma unroll
        for (int i = threadIdx.x; i < NE * DIM / 4; i += THREADS)
            Wsm[i] = Wg[i];
        if (threadIdx.x < NE) bs[threadIdx.x] = b[threadIdx.x];
    }
    __syncthreads();

    const int warp = threadIdx.x >> 5;
    const int lane = threadIdx.x & 31;
    const int token0 = (blockIdx.x * WARPS_PER_BLOCK + warp) * TOK_PER_WARP;
    if (token0 >= n_tokens) return;   // after the only __syncthreads: safe

    // Per-token base pointers, clamped for the partial last warp
    // (25216 = 24*1050 + 16). Hot loop stays guard-free.
    const float4* xp[TOK_PER_WARP];
    #pragma unroll
    for (int t = 0; t < TOK_PER_WARP; t++) {
        int tok = token0 + t;
        if (tok > n_tokens - 1) tok = n_tokens - 1;
        xp[t] = reinterpret_cast<const float4*>(x) + (size_t)tok * (DIM / 4) + lane;
    }

    // Flat partial sums: v[t*8 + e] for t<3; v[24..31] stay zero (padding so
    // the 32-wide transpose-reduce below is unchanged from the proven R13 one).
    float v[32];
    #pragma unroll
    for (int j = 0; j < 32; j++) v[j] = 0.0f;

    // Mainloop: per i, 3 independent coalesced LDG.128 (x stream) and
    // 8 LDS.128 (W, amortized over 3 tokens), 24 float4-dots.
    // Smem-port check: 1536 B DRAM per 32 smem-cyc = 48 B/cyc/SM > 42.6
    // needed for full HBM BW (TOK=2 would cap at 32 B/cyc).
    #pragma unroll
    for (int i = 0; i < F4_PER_LANE; i++) {
        float4 xv[TOK_PER_WARP];
        #pragma unroll
        for (int t = 0; t < TOK_PER_WARP; t++)
            xv[t] = xp[t][i * 32];
        #pragma unroll
        for (int e = 0; e < NE; e++) {
            const float4 wv =
                reinterpret_cast<const float4*>(Ws + e * DIM)[i * 32 + lane];
            #pragma unroll
            for (int t = 0; t < TOK_PER_WARP; t++)
                v[t * NE + e] += xv[t].x * wv.x + xv[t].y * wv.y +
                                 xv[t].z * wv.z + xv[t].w * wv.w;
        }
    }

    // Warp transpose-reduce: 32 slots -> 32 lanes in 31 shuffles.
    // Final: lane L holds the warp-wide sum of slot L.
    #pragma unroll
    for (int off = 16; off > 0; off >>= 1) {
        #pragma unroll
        for (int j = 0; j < off; j++) {
            const bool hi = (lane & off) != 0;
            float send = hi ? v[j] : v[j + off];
            float other = __shfl_xor_sync(0xffffffffu, send, off);
            v[j] = (hi ? v[j + off] : v[j]) + other;
        }
    }

    // Lane L owns logit for token t = L>>3, expert e = L&7 (t==3 is padding).
    const int t = lane >> 3;
    const int e = lane & 7;
    const int token = token0 + t;

    float logit = v[0] + bs[e];

    // Softmax over the 8-lane expert group (3+3 shuffles). Padding group
    // computes softmax of zeros (finite, discarded).
    float m = logit;
    #pragma unroll
    for (int off = 4; off > 0; off >>= 1)
        m = fmaxf(m, __shfl_xor_sync(0xffffffffu, m, off));
    float ex = __expf(logit - m);
    float s = ex;
    #pragma unroll
    for (int off = 4; off > 0; off >>= 1)
        s += __shfl_xor_sync(0xffffffffu, s, off);
    const float gate = ex / s;

    // Top-1 with lowest-index tie-break (matches jax.lax.top_k).
    float bv = gate; int bi = e;
    #pragma unroll
    for (int off = 4; off > 0; off >>= 1) {
        float ov = __shfl_xor_sync(0xffffffffu, bv, off);
        int   oi = __shfl_xor_sync(0xffffffffu, bi, off);
        if (ov > bv || (ov == bv && oi < bi)) { bv = ov; bi = oi; }
    }
    // Top-2: exclude the winner (gates > 0, so -1 is a safe sentinel).
    float cv = (e == bi) ? -1.0f : gate; int ci = e;
    #pragma unroll
    for (int off = 4; off > 0; off >>= 1) {
        float ov = __shfl_xor_sync(0xffffffffu, cv, off);
        int   oi = __shfl_xor_sync(0xffffffffu, ci, off);
        if (ov > cv || (ov == cv && oi < ci)) { cv = ov; ci = oi; }
    }

    // One writer lane per real token group.
    if (e == 0 && t < TOK_PER_WARP && token < n_tokens) {
        out[(size_t)token * 2 + 0] = bv;
        out[(size_t)token * 2 + 1] = cv;
        if (write_idx) {
            float* oi = out + (size_t)n_tokens * 2;
            oi[(size_t)token * 2 + 0] = (float)bi;   // float(int) exact
            oi[(size_t)token * 2 + 1] = (float)ci;
        }
    }
}

extern "C" void kernel_launch(void* const* d_in, const int* in_sizes, int n_in,
                              void* d_out, int out_size) {
    const float* x = (const float*)d_in[0];  // [128,197,768]
    const float* W = (const float*)d_in[1];  // [8,768]
    const float* b = (const float*)d_in[2];  // [8]
    float* out = (float*)d_out;

    const int n_tokens = in_sizes[0] / DIM;            // 25216
    const int write_idx = (out_size >= 4 * n_tokens);  // tuple packed: gates then idx

    const int grid = (n_tokens + TOK_PER_BLOCK - 1) / TOK_PER_BLOCK;  // 1051
    router_kernel<<<grid, THREADS>>>(x, W, b, out, n_tokens, write_idx);
}

// round 15
// speedup vs baseline: 1.4608x; 1.4608x over previous
#include <cuda_runtime.h>

#define DIM 768
#define NE 8
#define WARPS_PER_BLOCK 8
#define THREADS 256
#define TOK_PER_WARP 4
#define TOK_PER_BLOCK (WARPS_PER_BLOCK * TOK_PER_WARP)  // 32
// DIM/4 = 192 float4 per token row; 192/32 lanes = 6 float4 per lane
#define F4_PER_LANE 6

__global__ __launch_bounds__(THREADS, 4)   // caps regs at 64 -> 4 CTAs/SM
void router_kernel(const float* __restrict__ x,
                   const float* __restrict__ W,
                   const float* __restrict__ b,
                   float* __restrict__ out,
                   int n_tokens, int write_idx)
{
    __shared__ float Ws[NE * DIM];
    __shared__ float bs[NE];

    // Stage W (24 KB) + b into shared once per block, vectorized.
    {
        const float4* Wg = reinterpret_cast<const float4*>(W);
        float4* Wsm = reinterpret_cast<float4*>(Ws);
        #pragma unroll
        for (int i = threadIdx.x; i < NE * DIM / 4; i += THREADS)
            Wsm[i] = Wg[i];
        if (threadIdx.x < NE) bs[threadIdx.x] = b[threadIdx.x];
    }
    __syncthreads();

    const int warp = threadIdx.x >> 5;
    const int lane = threadIdx.x & 31;
    int token0 = (blockIdx.x * WARPS_PER_BLOCK + warp) * TOK_PER_WARP;
    if (token0 >= n_tokens) return;   // after the only __syncthreads: safe

    // Tail handling without hot-loop guards: shift the window back so all 4
    // tokens are in-bounds (n_tokens=25216 is divisible by 32, so this is a
    // no-op here; on ragged shapes two warps recompute identical values —
    // idempotent, deterministic).
    if (token0 > n_tokens - TOK_PER_WARP) token0 = n_tokens - TOK_PER_WARP;

    // Single base pointer; all per-(t,i) displacements are compile-time
    // immediates in the LDG encoding -> minimal address registers.
    const float4* xb = reinterpret_cast<const float4*>(x) +
                       (size_t)token0 * (DIM / 4) + lane;
    const float4* wb = reinterpret_cast<const float4*>(Ws) + lane;

    // Flat accumulators: v[t*8 + e]. After the transpose-reduce,
    // lane L holds the full sum of v[L].
    float v[TOK_PER_WARP * NE];
    #pragma unroll
    for (int j = 0; j < TOK_PER_WARP * NE; j++) v[j] = 0.0f;

    // Mainloop: per i, 4 independent coalesced LDG.128 (x stream) and
    // 8 LDS.128 (W, amortized over 4 tokens), 32 float4-dots.
    // l1tex cost: 48 wavefronts serving 4 tokens -> 72 wf/token
    // (24 LDG irreducible + 48 LDS).
    #pragma unroll
    for (int i = 0; i < F4_PER_LANE; i++) {
        float4 xv[TOK_PER_WARP];
        #pragma unroll
        for (int t = 0; t < TOK_PER_WARP; t++)
            xv[t] = xb[t * (DIM / 4) + i * 32];
        #pragma unroll
        for (int e = 0; e < NE; e++) {
            const float4 wv = wb[e * (DIM / 4) + i * 32];
            #pragma unroll
            for (int t = 0; t < TOK_PER_WARP; t++)
                v[t * NE + e] += xv[t].x * wv.x + xv[t].y * wv.y +
                                 xv[t].z * wv.z + xv[t].w * wv.w;
        }
    }

    // Warp transpose-reduce: 32 slots -> 32 lanes in 31 shuffles.
    // Final: lane L holds the warp-wide sum of slot L.
    #pragma unroll
    for (int off = 16; off > 0; off >>= 1) {
        #pragma unroll
        for (int j = 0; j < off; j++) {
            const bool hi = (lane & off) != 0;
            float send = hi ? v[j] : v[j + off];
            float other = __shfl_xor_sync(0xffffffffu, send, off);
            v[j] = (hi ? v[j + off] : v[j]) + other;
        }
    }

    // Lane L owns the logit for token t = L>>3, expert e = L&7.
    const int t = lane >> 3;
    const int e = lane & 7;
    const int token = token0 + t;

    float logit = v[0] + bs[e];

    // Softmax over the 8-lane expert group (3+3 shuffles).
    float m = logit;
    #pragma unroll
    for (int off = 4; off > 0; off >>= 1)
        m = fmaxf(m, __shfl_xor_sync(0xffffffffu, m, off));
    float ex = __expf(logit - m);
    float s = ex;
    #pragma unroll
    for (int off = 4; off > 0; off >>= 1)
        s += __shfl_xor_sync(0xffffffffu, s, off);
    const float gate = ex / s;

    // Top-1 with lowest-index tie-break (matches jax.lax.top_k).
    float bv = gate; int bi = e;
    #pragma unroll
    for (int off = 4; off > 0; off >>= 1) {
        float ov = __shfl_xor_sync(0xffffffffu, bv, off);
        int   oi = __shfl_xor_sync(0xffffffffu, bi, off);
        if (ov > bv || (ov == bv && oi < bi)) { bv = ov; bi = oi; }
    }
    // Top-2: exclude the winner (gates > 0, so -1 is a safe sentinel).
    float cv = (e == bi) ? -1.0f : gate; int ci = e;
    #pragma unroll
    for (int off = 4; off > 0; off >>= 1) {
        float ov = __shfl_xor_sync(0xffffffffu, cv, off);
        int   oi = __shfl_xor_sync(0xffffffffu, ci, off);
        if (ov > cv || (ov == cv && oi < ci)) { cv = ov; ci = oi; }
    }

    // One writer lane per token group.
    if (e == 0) {
        out[(size_t)token * 2 + 0] = bv;
        out[(size_t)token * 2 + 1] = cv;
        if (write_idx) {
            float* oi = out + (size_t)n_tokens * 2;
            oi[(size_t)token * 2 + 0] = (float)bi;   // float(int) exact
            oi[(size_t)token * 2 + 1] = (float)ci;
        }
    }
}

extern "C" void kernel_launch(void* const* d_in, const int* in_sizes, int n_in,
                              void* d_out, int out_size) {
    const float* x = (const float*)d_in[0];  // [128,197,768]
    const float* W = (const float*)d_in[1];  // [8,768]
    const float* b = (const float*)d_in[2];  // [8]
    float* out = (float*)d_out;

    const int n_tokens = in_sizes[0] / DIM;            // 25216
    const int write_idx = (out_size >= 4 * n_tokens);  // tuple packed: gates then idx

    const int grid = (n_tokens + TOK_PER_BLOCK - 1) / TOK_PER_BLOCK;  // 788
    router_kernel<<<grid, THREADS>>>(x, W, b, out, n_tokens, write_idx);
}